// round 1
// baseline (speedup 1.0000x reference)
#include <cuda_runtime.h>
#include <cstdint>

// ---------------------------------------------------------------------------
// Problem constants
// ---------------------------------------------------------------------------
#define BATCH     2
#define SEQ       8192
#define EMB       1024
#define NHEAD     16
#define DHEAD     64
#define QKV_N     3072
#define MTOT      (BATCH * SEQ)      // 16384 rows

// ---------------------------------------------------------------------------
// Device scratch (allocation-free: __device__ globals)
// ---------------------------------------------------------------------------
__device__ float g_qkv [ (size_t)MTOT * QKV_N ];   // 201 MB
__device__ float g_attn[ (size_t)MTOT * EMB   ];   // 67 MB
__device__ int   g_order32[1024];
__device__ int   g_order64[4096];
// token gather table: group0 (len 1024) at [0,1024); groups 1..14 (len 512)
// at 1024 + (g-1)*512. g_tok[slot] = original sequence position (0..8191).
__device__ int   g_tok[SEQ];

// ---------------------------------------------------------------------------
// Hilbert curve d-index (matches reference _xy2d exactly)
// ---------------------------------------------------------------------------
__device__ __forceinline__ int xy2d(int nside, int x, int y) {
    int d = 0;
    for (int s = nside >> 1; s > 0; s >>= 1) {
        int rx = (x & s) ? 1 : 0;
        int ry = (y & s) ? 1 : 0;
        d += s * s * ((3 * rx) ^ ry);
        if (ry == 0) {
            if (rx == 1) { x = s - 1 - x; y = s - 1 - y; }
            int t = x; x = y; y = t;
        }
    }
    return d;
}

__global__ void build_orders_kernel() {
    int id = blockIdx.x * blockDim.x + threadIdx.x;
    if (id < 1024) {
        int x = id & 31, y = id >> 5;
        g_order32[xy2d(32, x, y)] = id;
    }
    if (id < 4096) {
        int x = id & 63, y = id >> 6;
        g_order64[xy2d(64, x, y)] = id;
    }
}

// Single block, 1024 threads. Builds g_tok for all 4 segments, including the
// L=2048 compaction (order64 entries < 2048, order preserved).
__global__ void build_tok_kernel() {
    __shared__ int cnt[1024];
    __shared__ int perm2048[2048];
    int t = threadIdx.x;

    // --- compaction of g_order64 (< 2048), each thread owns 4 entries ---
    int v[4]; int c = 0;
    #pragma unroll
    for (int w = 0; w < 4; w++) {
        v[w] = g_order64[t * 4 + w];
        c += (v[w] < 2048) ? 1 : 0;
    }
    cnt[t] = c;
    __syncthreads();
    // Hillis-Steele inclusive scan over 1024 counts
    for (int off = 1; off < 1024; off <<= 1) {
        int add = (t >= off) ? cnt[t - off] : 0;
        __syncthreads();
        cnt[t] += add;
        __syncthreads();
    }
    int pos = cnt[t] - c;   // exclusive prefix
    #pragma unroll
    for (int w = 0; w < 4; w++) {
        if (v[w] < 2048) perm2048[pos++] = v[w];
    }
    __syncthreads();

    // --- segment 0: L=1024, rate=1, start 0. perm = order32. ---
    g_tok[t] = g_order32[t];

    // --- segment 1: L=1024, rate=2, start 1024. group p, row j: perm[j*2+p] ---
    {
        int p = t >> 9, j = t & 511;
        g_tok[1024 + p * 512 + j] = 1024 + g_order32[j * 2 + p];
    }

    // --- segment 2: L=2048, rate=4, start 2048. perm = compacted order64 ---
    for (int e = t; e < 2048; e += 1024) {
        int p = e >> 9, j = e & 511;
        g_tok[2048 + e] = 2048 + perm2048[j * 4 + p];
    }

    // --- segment 3: L=4096, rate=8, start 4096. perm = order64. ---
    for (int e = t; e < 4096; e += 1024) {
        int p = e >> 9, j = e & 511;
        g_tok[4096 + e] = 4096 + g_order64[j * 8 + p];
    }
}

// ---------------------------------------------------------------------------
// GEMM: C[M,N] = A[M,K] * B[N,K]^T + bias[N]   (both operands K-contiguous)
// 128x128 tile, BK=8, 256 threads, 8x8 per thread. M,N multiples of 128,
// K multiple of 8 (true for all call sites — no bounds checks).
// ---------------------------------------------------------------------------
__global__ __launch_bounds__(256, 2)
void gemm_nt_bias_kernel(const float* __restrict__ A,
                         const float* __restrict__ B,
                         const float* __restrict__ bias,
                         float* __restrict__ C,
                         int M, int N, int K)
{
    __shared__ float As[8][128];
    __shared__ float Bs[8][128];

    int tid = threadIdx.x;
    int m0 = blockIdx.y * 128;
    int n0 = blockIdx.x * 128;

    int lr = tid >> 1;             // 0..127 (tile row for loads)
    int lc = (tid & 1) * 4;        // 0 or 4 (k-offset for loads)
    const float* Ap = A + (size_t)(m0 + lr) * K + lc;
    const float* Bp = B + (size_t)(n0 + lr) * K + lc;

    int ty = tid >> 4, tx = tid & 15;

    float acc[8][8];
    #pragma unroll
    for (int i = 0; i < 8; i++)
        #pragma unroll
        for (int j = 0; j < 8; j++) acc[i][j] = 0.f;

    for (int kb = 0; kb < K; kb += 8) {
        float4 av = *(const float4*)(Ap + kb);
        float4 bv = *(const float4*)(Bp + kb);
        __syncthreads();
        As[lc + 0][lr] = av.x; As[lc + 1][lr] = av.y;
        As[lc + 2][lr] = av.z; As[lc + 3][lr] = av.w;
        Bs[lc + 0][lr] = bv.x; Bs[lc + 1][lr] = bv.y;
        Bs[lc + 2][lr] = bv.z; Bs[lc + 3][lr] = bv.w;
        __syncthreads();

        #pragma unroll
        for (int k = 0; k < 8; k++) {
            float a[8], b[8];
            *(float4*)(a)     = *(const float4*)&As[k][ty * 8];
            *(float4*)(a + 4) = *(const float4*)&As[k][ty * 8 + 4];
            *(float4*)(b)     = *(const float4*)&Bs[k][tx * 8];
            *(float4*)(b + 4) = *(const float4*)&Bs[k][tx * 8 + 4];
            #pragma unroll
            for (int i = 0; i < 8; i++)
                #pragma unroll
                for (int j = 0; j < 8; j++)
                    acc[i][j] = fmaf(a[i], b[j], acc[i][j]);
        }
    }

    // epilogue
    int nbase = n0 + tx * 8;
    float bvv[8];
    #pragma unroll
    for (int j = 0; j < 8; j++) bvv[j] = bias[nbase + j];

    #pragma unroll
    for (int i = 0; i < 8; i++) {
        int m = m0 + ty * 8 + i;
        float* cp = C + (size_t)m * N + nbase;
        float4 r0, r1;
        r0.x = acc[i][0] + bvv[0]; r0.y = acc[i][1] + bvv[1];
        r0.z = acc[i][2] + bvv[2]; r0.w = acc[i][3] + bvv[3];
        r1.x = acc[i][4] + bvv[4]; r1.y = acc[i][5] + bvv[5];
        r1.z = acc[i][6] + bvv[6]; r1.w = acc[i][7] + bvv[7];
        *(float4*)(cp)     = r0;
        *(float4*)(cp + 4) = r1;
    }
}

// ---------------------------------------------------------------------------
// Flash-style attention over gathered groups.
// grid.x = 128 q-tiles (16 for group0 len 1024, 8 each for groups 1..14
// len 512), grid.y = B*H = 32. Block = 256 threads (16x16), BM=BN=64, D=64.
// Q pre-scaled by 1/8. K stored transposed in smem (conflict-free float4
// reads); P aliases the K tile after scores are consumed.
// ---------------------------------------------------------------------------
__global__ __launch_bounds__(256, 2)
void attn_kernel()
{
    __shared__ float Qs[64][64];
    __shared__ float Kt[64][64];   // K transposed: Kt[d][j]; later reused as P[row][j]
    __shared__ float Vs[64][64];

    int by = blockIdx.y;
    int bb = by >> 4;
    int h  = by & 15;

    int ti = blockIdx.x;
    int qt, n, toff;
    if (ti < 16) { qt = ti; n = 1024; toff = 0; }
    else {
        int g = 1 + ((ti - 16) >> 3);
        qt = (ti - 16) & 7;
        n = 512;
        toff = 1024 + (g - 1) * 512;
    }

    int tid = threadIdx.x;
    int ty = tid >> 4, tx = tid & 15;
    int lrow = tid >> 2;            // 0..63 (load row)
    int lq   = (tid & 3) << 4;      // 0,16,32,48 (load column base)

    const float scale = 0.125f;     // 1/sqrt(64)
    size_t bh_base = (size_t)bb * SEQ * QKV_N + (size_t)h * DHEAD;

    // ---- load Q tile (pre-scaled) ----
    {
        int t = g_tok[toff + qt * 64 + lrow];
        const float* p = g_qkv + bh_base + (size_t)t * QKV_N;
        #pragma unroll
        for (int w = 0; w < 16; w += 4) {
            float4 v = *(const float4*)(p + lq + w);
            float4 s4;
            s4.x = v.x * scale; s4.y = v.y * scale;
            s4.z = v.z * scale; s4.w = v.w * scale;
            *(float4*)&Qs[lrow][lq + w] = s4;
        }
    }

    float m_[4], l_[4], o_[4][4];
    #pragma unroll
    for (int i = 0; i < 4; i++) {
        m_[i] = -1e30f; l_[i] = 0.f;
        #pragma unroll
        for (int j = 0; j < 4; j++) o_[i][j] = 0.f;
    }

    int nkt = n >> 6;
    for (int kt = 0; kt < nkt; kt++) {
        __syncthreads();  // previous iteration done with Kt(P)/Vs
        // ---- load K (transposed) + V ----
        {
            int t = g_tok[toff + kt * 64 + lrow];
            const float* kp = g_qkv + bh_base + (size_t)t * QKV_N + EMB;
            const float* vp = kp + EMB;
            #pragma unroll
            for (int w = 0; w < 16; w += 4) {
                float4 kv = *(const float4*)(kp + lq + w);
                Kt[lq + w + 0][lrow] = kv.x;
                Kt[lq + w + 1][lrow] = kv.y;
                Kt[lq + w + 2][lrow] = kv.z;
                Kt[lq + w + 3][lrow] = kv.w;
                *(float4*)&Vs[lrow][lq + w] = *(const float4*)(vp + lq + w);
            }
        }
        __syncthreads();

        // ---- scores: s[i][j] = sum_d Q[ty*4+i][d] * K[tx*4+j][d] ----
        float s[4][4];
        #pragma unroll
        for (int i = 0; i < 4; i++)
            #pragma unroll
            for (int j = 0; j < 4; j++) s[i][j] = 0.f;

        #pragma unroll 8
        for (int kk = 0; kk < 64; kk++) {
            float a0 = Qs[ty * 4 + 0][kk];
            float a1 = Qs[ty * 4 + 1][kk];
            float a2 = Qs[ty * 4 + 2][kk];
            float a3 = Qs[ty * 4 + 3][kk];
            float4 bq = *(const float4*)&Kt[kk][tx * 4];
            s[0][0] = fmaf(a0, bq.x, s[0][0]); s[0][1] = fmaf(a0, bq.y, s[0][1]);
            s[0][2] = fmaf(a0, bq.z, s[0][2]); s[0][3] = fmaf(a0, bq.w, s[0][3]);
            s[1][0] = fmaf(a1, bq.x, s[1][0]); s[1][1] = fmaf(a1, bq.y, s[1][1]);
            s[1][2] = fmaf(a1, bq.z, s[1][2]); s[1][3] = fmaf(a1, bq.w, s[1][3]);
            s[2][0] = fmaf(a2, bq.x, s[2][0]); s[2][1] = fmaf(a2, bq.y, s[2][1]);
            s[2][2] = fmaf(a2, bq.z, s[2][2]); s[2][3] = fmaf(a2, bq.w, s[2][3]);
            s[3][0] = fmaf(a3, bq.x, s[3][0]); s[3][1] = fmaf(a3, bq.y, s[3][1]);
            s[3][2] = fmaf(a3, bq.z, s[3][2]); s[3][3] = fmaf(a3, bq.w, s[3][3]);
        }

        // ---- online softmax (rows shared across the 16-lane tx group) ----
        float p_[4][4];
        #pragma unroll
        for (int i = 0; i < 4; i++) {
            float rm = fmaxf(fmaxf(s[i][0], s[i][1]), fmaxf(s[i][2], s[i][3]));
            #pragma unroll
            for (int off = 8; off > 0; off >>= 1)
                rm = fmaxf(rm, __shfl_xor_sync(0xffffffffu, rm, off));
            float mnew = fmaxf(m_[i], rm);
            float alpha = __expf(m_[i] - mnew);
            float rs = 0.f;
            #pragma unroll
            for (int j = 0; j < 4; j++) {
                p_[i][j] = __expf(s[i][j] - mnew);
                rs += p_[i][j];
            }
            #pragma unroll
            for (int off = 8; off > 0; off >>= 1)
                rs += __shfl_xor_sync(0xffffffffu, rs, off);
            l_[i] = l_[i] * alpha + rs;
            m_[i] = mnew;
            #pragma unroll
            for (int j = 0; j < 4; j++) o_[i][j] *= alpha;
        }

        __syncthreads();  // everyone done reading Kt
        // ---- stash P into the Kt buffer (row-major P[row][j]) ----
        #pragma unroll
        for (int i = 0; i < 4; i++)
            #pragma unroll
            for (int j = 0; j < 4; j++)
                Kt[ty * 4 + i][tx * 4 + j] = p_[i][j];
        __syncthreads();

        // ---- O += P * V ----
        #pragma unroll 8
        for (int j = 0; j < 64; j++) {
            float4 v = *(const float4*)&Vs[j][tx * 4];
            float p0 = Kt[ty * 4 + 0][j];
            float p1 = Kt[ty * 4 + 1][j];
            float p2 = Kt[ty * 4 + 2][j];
            float p3 = Kt[ty * 4 + 3][j];
            o_[0][0] = fmaf(p0, v.x, o_[0][0]); o_[0][1] = fmaf(p0, v.y, o_[0][1]);
            o_[0][2] = fmaf(p0, v.z, o_[0][2]); o_[0][3] = fmaf(p0, v.w, o_[0][3]);
            o_[1][0] = fmaf(p1, v.x, o_[1][0]); o_[1][1] = fmaf(p1, v.y, o_[1][1]);
            o_[1][2] = fmaf(p1, v.z, o_[1][2]); o_[1][3] = fmaf(p1, v.w, o_[1][3]);
            o_[2][0] = fmaf(p2, v.x, o_[2][0]); o_[2][1] = fmaf(p2, v.y, o_[2][1]);
            o_[2][2] = fmaf(p2, v.z, o_[2][2]); o_[2][3] = fmaf(p2, v.w, o_[2][3]);
            o_[3][0] = fmaf(p3, v.x, o_[3][0]); o_[3][1] = fmaf(p3, v.y, o_[3][1]);
            o_[3][2] = fmaf(p3, v.z, o_[3][2]); o_[3][3] = fmaf(p3, v.w, o_[3][3]);
        }
    }

    // ---- normalize + scatter to g_attn in [B,S,H*D] layout ----
    #pragma unroll
    for (int i = 0; i < 4; i++) {
        int row = ty * 4 + i;
        int t = g_tok[toff + qt * 64 + row];
        float inv = 1.f / l_[i];
        float4 r;
        r.x = o_[i][0] * inv; r.y = o_[i][1] * inv;
        r.z = o_[i][2] * inv; r.w = o_[i][3] * inv;
        float* op = g_attn + ((size_t)bb * SEQ + t) * EMB + h * DHEAD + tx * 4;
        *(float4*)op = r;
    }
}

// ---------------------------------------------------------------------------
// Launch
// ---------------------------------------------------------------------------
extern "C" void kernel_launch(void* const* d_in, const int* in_sizes, int n_in,
                              void* d_out, int out_size)
{
    const float* x      = (const float*)d_in[0];
    const float* w_qkv  = (const float*)d_in[1];
    const float* b_qkv  = (const float*)d_in[2];
    const float* w_out  = (const float*)d_in[3];
    const float* b_out  = (const float*)d_in[4];
    float* out          = (float*)d_out;

    float* qkv_buf = nullptr;
    float* attn_buf = nullptr;
    cudaGetSymbolAddress((void**)&qkv_buf,  g_qkv);
    cudaGetSymbolAddress((void**)&attn_buf, g_attn);

    // 1) Hilbert order tables + token gather table
    build_orders_kernel<<<16, 256>>>();
    build_tok_kernel<<<1, 1024>>>();

    // 2) QKV projection: [16384,1024] x [3072,1024]^T
    {
        dim3 grid(QKV_N / 128, MTOT / 128);
        gemm_nt_bias_kernel<<<grid, 256>>>(x, w_qkv, b_qkv, qkv_buf,
                                           MTOT, QKV_N, EMB);
    }

    // 3) Segmented dilated attention (15 groups per (B,H))
    {
        dim3 grid(128, BATCH * NHEAD);
        attn_kernel<<<grid, 256>>>();
    }

    // 4) Output projection: [16384,1024] x [1024,1024]^T
    {
        dim3 grid(EMB / 128, MTOT / 128);
        gemm_nt_bias_kernel<<<grid, 256>>>(attn_buf, w_out, b_out, out,
                                           MTOT, EMB, EMB);
    }
}

// round 3
// speedup vs baseline: 1.9290x; 1.9290x over previous
#include <cuda_runtime.h>
#include <cuda_bf16.h>
#include <cstdint>

// ---------------------------------------------------------------------------
// Problem constants
// ---------------------------------------------------------------------------
#define BATCH     2
#define SEQ       8192
#define EMB       1024
#define NHEAD     16
#define DHEAD     64
#define QKV_N     3072
#define MTOT      (BATCH * SEQ)      // 16384 rows

// ---------------------------------------------------------------------------
// Device scratch (allocation-free: __device__ globals)
// ---------------------------------------------------------------------------
__device__ float          g_qkv[(size_t)MTOT * QKV_N];     // fp32 qkv
__device__ __nv_bfloat16  g_xh [(size_t)MTOT * EMB];
__device__ __nv_bfloat16  g_xl [(size_t)MTOT * EMB];
__device__ __nv_bfloat16  g_wqh[(size_t)QKV_N * EMB];
__device__ __nv_bfloat16  g_wql[(size_t)QKV_N * EMB];
__device__ __nv_bfloat16  g_ah [(size_t)MTOT * EMB];
__device__ __nv_bfloat16  g_al [(size_t)MTOT * EMB];
__device__ __nv_bfloat16  g_woh[(size_t)EMB * EMB];
__device__ __nv_bfloat16  g_wol[(size_t)EMB * EMB];
__device__ int g_order32[1024];
__device__ int g_order64[4096];
__device__ int g_tok[SEQ];

// ---------------------------------------------------------------------------
// Base-ISA helpers (sm_80+/sm_75+: cp.async, ldmatrix, mma.sync)
// ---------------------------------------------------------------------------
__device__ __forceinline__ uint32_t smem_u32(const void* p) {
    uint32_t a;
    asm("{ .reg .u64 t; cvta.to.shared.u64 t, %1; cvt.u32.u64 %0, t; }"
        : "=r"(a) : "l"(p));
    return a;
}
__device__ __forceinline__ void cp16(uint32_t s, const void* g) {
    asm volatile("cp.async.cg.shared.global [%0], [%1], 16;"
                 :: "r"(s), "l"(g) : "memory");
}
__device__ __forceinline__ void cp_commit() {
    asm volatile("cp.async.commit_group;" ::: "memory");
}
template<int N>
__device__ __forceinline__ void cp_wait() {
    asm volatile("cp.async.wait_group %0;" :: "n"(N) : "memory");
}
__device__ __forceinline__ void ldsm_x4(uint32_t* r, uint32_t a) {
    asm volatile("ldmatrix.sync.aligned.m8n8.x4.shared.b16 {%0,%1,%2,%3}, [%4];"
                 : "=r"(r[0]), "=r"(r[1]), "=r"(r[2]), "=r"(r[3]) : "r"(a));
}
__device__ __forceinline__ void mma_bf16(float* c, const uint32_t* a,
                                         const uint32_t b0, const uint32_t b1) {
    asm volatile(
        "mma.sync.aligned.m16n8k16.row.col.f32.bf16.bf16.f32 "
        "{%0,%1,%2,%3}, {%4,%5,%6,%7}, {%8,%9}, {%0,%1,%2,%3};"
        : "+f"(c[0]), "+f"(c[1]), "+f"(c[2]), "+f"(c[3])
        : "r"(a[0]), "r"(a[1]), "r"(a[2]), "r"(a[3]), "r"(b0), "r"(b1));
}
// smem layout: 32-bf16 rows (64B); 16B-chunk swizzle for conflict-free ldmatrix
__device__ __forceinline__ uint32_t swz(int r, int c) {
    return (uint32_t)(r * 64 + ((c ^ ((r >> 1) & 3)) << 4));
}

// ---------------------------------------------------------------------------
// hi/lo bf16 split kernel (fp32 -> bf16 pair), 4 elements/thread
// ---------------------------------------------------------------------------
__global__ void split_kernel(const float* __restrict__ s,
                             __nv_bfloat16* __restrict__ hi,
                             __nv_bfloat16* __restrict__ lo, int n4) {
    int i = blockIdx.x * blockDim.x + threadIdx.x;
    if (i >= n4) return;
    float4 v = ((const float4*)s)[i];
    __nv_bfloat16 h0 = __float2bfloat16(v.x);
    __nv_bfloat16 h1 = __float2bfloat16(v.y);
    __nv_bfloat16 h2 = __float2bfloat16(v.z);
    __nv_bfloat16 h3 = __float2bfloat16(v.w);
    __nv_bfloat16 l0 = __float2bfloat16(v.x - __bfloat162float(h0));
    __nv_bfloat16 l1 = __float2bfloat16(v.y - __bfloat162float(h1));
    __nv_bfloat16 l2 = __float2bfloat16(v.z - __bfloat162float(h2));
    __nv_bfloat16 l3 = __float2bfloat16(v.w - __bfloat162float(h3));
    __nv_bfloat162* hp = (__nv_bfloat162*)hi + 2 * (size_t)i;
    __nv_bfloat162* lp = (__nv_bfloat162*)lo + 2 * (size_t)i;
    hp[0] = __halves2bfloat162(h0, h1);
    hp[1] = __halves2bfloat162(h2, h3);
    lp[0] = __halves2bfloat162(l0, l1);
    lp[1] = __halves2bfloat162(l2, l3);
}

// ---------------------------------------------------------------------------
// Hilbert tables
// ---------------------------------------------------------------------------
__device__ __forceinline__ int xy2d(int nside, int x, int y) {
    int d = 0;
    for (int s = nside >> 1; s > 0; s >>= 1) {
        int rx = (x & s) ? 1 : 0;
        int ry = (y & s) ? 1 : 0;
        d += s * s * ((3 * rx) ^ ry);
        if (ry == 0) {
            if (rx == 1) { x = s - 1 - x; y = s - 1 - y; }
            int t = x; x = y; y = t;
        }
    }
    return d;
}

__global__ void build_orders_kernel() {
    int id = blockIdx.x * blockDim.x + threadIdx.x;
    if (id < 1024) { int x = id & 31, y = id >> 5; g_order32[xy2d(32, x, y)] = id; }
    if (id < 4096) { int x = id & 63, y = id >> 6; g_order64[xy2d(64, x, y)] = id; }
}

__global__ void build_tok_kernel() {
    __shared__ int cnt[1024];
    __shared__ int perm2048[2048];
    int t = threadIdx.x;
    int v[4]; int c = 0;
    #pragma unroll
    for (int w = 0; w < 4; w++) {
        v[w] = g_order64[t * 4 + w];
        c += (v[w] < 2048) ? 1 : 0;
    }
    cnt[t] = c;
    __syncthreads();
    for (int off = 1; off < 1024; off <<= 1) {
        int add = (t >= off) ? cnt[t - off] : 0;
        __syncthreads();
        cnt[t] += add;
        __syncthreads();
    }
    int pos = cnt[t] - c;
    #pragma unroll
    for (int w = 0; w < 4; w++) if (v[w] < 2048) perm2048[pos++] = v[w];
    __syncthreads();

    g_tok[t] = g_order32[t];
    { int p = t >> 9, j = t & 511; g_tok[1024 + p * 512 + j] = 1024 + g_order32[j * 2 + p]; }
    for (int e = t; e < 2048; e += 1024) {
        int p = e >> 9, j = e & 511;
        g_tok[2048 + e] = 2048 + perm2048[j * 4 + p];
    }
    for (int e = t; e < 4096; e += 1024) {
        int p = e >> 9, j = e & 511;
        g_tok[4096 + e] = 4096 + g_order64[j * 8 + p];
    }
}

// ---------------------------------------------------------------------------
// mma.sync bf16x3 GEMM:  C[M,N] = (Ah+Al)[M,K] * (Bh+Bl)[N,K]^T + bias[N]
// (hi*hi + hi*lo + lo*hi, fp32 accumulators)
// CTA tile 128x128, BK=32, 256 threads = 8 warps (2m x 4n), warp tile 64x32.
// cp.async double-buffered. Requires M%128==0, N%128==0, K%32==0.
// ---------------------------------------------------------------------------
#define G_STAGE 32768                 // bytes per stage (4 matrices x 8KB)
#define G_AH 0
#define G_AL 8192
#define G_BH 16384
#define G_BL 24576
#define GEMM_SMEM (2 * G_STAGE)       // 64 KB

__global__ __launch_bounds__(256)
void gemm_bf16x3_mma(const __nv_bfloat16* __restrict__ Ah,
                     const __nv_bfloat16* __restrict__ Al,
                     const __nv_bfloat16* __restrict__ Bh,
                     const __nv_bfloat16* __restrict__ Bl,
                     const float* __restrict__ bias,
                     float* __restrict__ C,
                     int M, int N, int K)
{
    extern __shared__ char sm[];
    uint32_t sb = smem_u32(sm);

    int tid = threadIdx.x;
    int lane = tid & 31;
    int wid = tid >> 5;
    int wm = wid >> 2;      // 0..1 -> m offset 64*wm
    int wn = wid & 3;       // 0..3 -> n offset 32*wn
    int m0 = blockIdx.y * 128;
    int n0 = blockIdx.x * 128;

    // per-thread load coords: chunk i = tid (and tid+256); r=i>>2, c=i&3
    int lr0 = tid >> 2, lc = tid & 3;        // rows 0..63
    int lr1 = lr0 + 64;                      // rows 64..127
    uint32_t so0 = swz(lr0, lc), so1 = swz(lr1, lc);
    // gmem element offsets (row*K + c*8), row relative to tile
    const __nv_bfloat16* gAh0 = Ah + (size_t)(m0 + lr0) * K + lc * 8;
    const __nv_bfloat16* gAh1 = Ah + (size_t)(m0 + lr1) * K + lc * 8;
    const __nv_bfloat16* gAl0 = Al + (size_t)(m0 + lr0) * K + lc * 8;
    const __nv_bfloat16* gAl1 = Al + (size_t)(m0 + lr1) * K + lc * 8;
    const __nv_bfloat16* gBh0 = Bh + (size_t)(n0 + lr0) * K + lc * 8;
    const __nv_bfloat16* gBh1 = Bh + (size_t)(n0 + lr1) * K + lc * 8;
    const __nv_bfloat16* gBl0 = Bl + (size_t)(n0 + lr0) * K + lc * 8;
    const __nv_bfloat16* gBl1 = Bl + (size_t)(n0 + lr1) * K + lc * 8;

    float acc[4][4][4];
    #pragma unroll
    for (int i = 0; i < 4; i++)
        #pragma unroll
        for (int j = 0; j < 4; j++)
            #pragma unroll
            for (int e = 0; e < 4; e++) acc[i][j][e] = 0.f;

    // ldmatrix source addresses (per warp)
    // A x4: rows = wm*64 + mt*16 + (lane&15), chunk = ks*2 + (lane>>4)
    int arow = wm * 64 + (lane & 15);
    int akc  = lane >> 4;
    // B x4 (2 n-tiles): rows = wn*32 + ntp*16 + ((lane>>4)&1)*8 + (lane&7),
    //                   chunk = ks*2 + ((lane>>3)&1)
    int brow = wn * 32 + ((lane >> 4) & 1) * 8 + (lane & 7);
    int bkc  = (lane >> 3) & 1;

    int nkc = K >> 5;

    // prologue: stage 0
    {
        cp16(sb + 0 * G_STAGE + G_AH + so0, gAh0);
        cp16(sb + 0 * G_STAGE + G_AH + so1, gAh1);
        cp16(sb + 0 * G_STAGE + G_AL + so0, gAl0);
        cp16(sb + 0 * G_STAGE + G_AL + so1, gAl1);
        cp16(sb + 0 * G_STAGE + G_BH + so0, gBh0);
        cp16(sb + 0 * G_STAGE + G_BH + so1, gBh1);
        cp16(sb + 0 * G_STAGE + G_BL + so0, gBl0);
        cp16(sb + 0 * G_STAGE + G_BL + so1, gBl1);
        cp_commit();
    }

    for (int kc = 0; kc < nkc; kc++) {
        if (kc + 1 < nkc) {
            uint32_t st = sb + ((kc + 1) & 1) * G_STAGE;
            int ke = (kc + 1) * 32;
            cp16(st + G_AH + so0, gAh0 + ke);
            cp16(st + G_AH + so1, gAh1 + ke);
            cp16(st + G_AL + so0, gAl0 + ke);
            cp16(st + G_AL + so1, gAl1 + ke);
            cp16(st + G_BH + so0, gBh0 + ke);
            cp16(st + G_BH + so1, gBh1 + ke);
            cp16(st + G_BL + so0, gBl0 + ke);
            cp16(st + G_BL + so1, gBl1 + ke);
            cp_commit();
            cp_wait<1>();
        } else {
            cp_wait<0>();
        }
        __syncthreads();

        uint32_t sA = sb + (kc & 1) * G_STAGE;
        #pragma unroll
        for (int ks = 0; ks < 2; ks++) {
            uint32_t ah[4][4], al[4][4];
            #pragma unroll
            for (int mt = 0; mt < 4; mt++) {
                uint32_t off = swz(arow + mt * 16, ks * 2 + akc);
                ldsm_x4(ah[mt], sA + G_AH + off);
                ldsm_x4(al[mt], sA + G_AL + off);
            }
            uint32_t bh[4][2], bl[4][2];
            #pragma unroll
            for (int ntp = 0; ntp < 2; ntp++) {
                uint32_t off = swz(brow + ntp * 16, ks * 2 + bkc);
                uint32_t t4[4];
                ldsm_x4(t4, sA + G_BH + off);
                bh[ntp * 2][0] = t4[0]; bh[ntp * 2][1] = t4[1];
                bh[ntp * 2 + 1][0] = t4[2]; bh[ntp * 2 + 1][1] = t4[3];
                ldsm_x4(t4, sA + G_BL + off);
                bl[ntp * 2][0] = t4[0]; bl[ntp * 2][1] = t4[1];
                bl[ntp * 2 + 1][0] = t4[2]; bl[ntp * 2 + 1][1] = t4[3];
            }
            #pragma unroll
            for (int mt = 0; mt < 4; mt++)
                #pragma unroll
                for (int nt = 0; nt < 4; nt++) {
                    mma_bf16(acc[mt][nt], ah[mt], bh[nt][0], bh[nt][1]);
                    mma_bf16(acc[mt][nt], ah[mt], bl[nt][0], bl[nt][1]);
                    mma_bf16(acc[mt][nt], al[mt], bh[nt][0], bh[nt][1]);
                }
        }
        __syncthreads();
    }

    // epilogue: bias add + fp32 store (cols even -> aligned float2)
    #pragma unroll
    for (int mt = 0; mt < 4; mt++) {
        int m = m0 + wm * 64 + mt * 16 + (lane >> 2);
        #pragma unroll
        for (int nt = 0; nt < 4; nt++) {
            int n = n0 + wn * 32 + nt * 8 + (lane & 3) * 2;
            float b0 = bias[n], b1 = bias[n + 1];
            float2 r0 = make_float2(acc[mt][nt][0] + b0, acc[mt][nt][1] + b1);
            float2 r1 = make_float2(acc[mt][nt][2] + b0, acc[mt][nt][3] + b1);
            *(float2*)(C + (size_t)m * N + n) = r0;
            *(float2*)(C + (size_t)(m + 8) * N + n) = r1;
        }
    }
}

// ---------------------------------------------------------------------------
// Flash-style fp32 attention; epilogue writes bf16 hi/lo for the out-proj
// ---------------------------------------------------------------------------
__global__ __launch_bounds__(256, 2)
void attn_kernel()
{
    __shared__ float Qs[64][64];
    __shared__ float Kt[64][64];   // K transposed; reused as P
    __shared__ float Vs[64][64];

    int by = blockIdx.y;
    int bb = by >> 4;
    int hd = by & 15;

    int ti = blockIdx.x;
    int qt, n, toff;
    if (ti < 16) { qt = ti; n = 1024; toff = 0; }
    else {
        int g = 1 + ((ti - 16) >> 3);
        qt = (ti - 16) & 7;
        n = 512;
        toff = 1024 + (g - 1) * 512;
    }

    int tid = threadIdx.x;
    int ty = tid >> 4, tx = tid & 15;
    int lrow = tid >> 2;
    int lq   = (tid & 3) << 4;

    const float scale = 0.125f;
    size_t bh_base = (size_t)bb * SEQ * QKV_N + (size_t)hd * DHEAD;

    {
        int t = g_tok[toff + qt * 64 + lrow];
        const float* p = g_qkv + bh_base + (size_t)t * QKV_N;
        #pragma unroll
        for (int w = 0; w < 16; w += 4) {
            float4 v = *(const float4*)(p + lq + w);
            float4 s4;
            s4.x = v.x * scale; s4.y = v.y * scale;
            s4.z = v.z * scale; s4.w = v.w * scale;
            *(float4*)&Qs[lrow][lq + w] = s4;
        }
    }

    float m_[4], l_[4], o_[4][4];
    #pragma unroll
    for (int i = 0; i < 4; i++) {
        m_[i] = -1e30f; l_[i] = 0.f;
        #pragma unroll
        for (int j = 0; j < 4; j++) o_[i][j] = 0.f;
    }

    int nkt = n >> 6;
    for (int kt = 0; kt < nkt; kt++) {
        __syncthreads();
        {
            int t = g_tok[toff + kt * 64 + lrow];
            const float* kp = g_qkv + bh_base + (size_t)t * QKV_N + EMB;
            const float* vp = kp + EMB;
            #pragma unroll
            for (int w = 0; w < 16; w += 4) {
                float4 kv = *(const float4*)(kp + lq + w);
                Kt[lq + w + 0][lrow] = kv.x;
                Kt[lq + w + 1][lrow] = kv.y;
                Kt[lq + w + 2][lrow] = kv.z;
                Kt[lq + w + 3][lrow] = kv.w;
                *(float4*)&Vs[lrow][lq + w] = *(const float4*)(vp + lq + w);
            }
        }
        __syncthreads();

        float s[4][4];
        #pragma unroll
        for (int i = 0; i < 4; i++)
            #pragma unroll
            for (int j = 0; j < 4; j++) s[i][j] = 0.f;

        #pragma unroll 8
        for (int kk = 0; kk < 64; kk++) {
            float a0 = Qs[ty * 4 + 0][kk];
            float a1 = Qs[ty * 4 + 1][kk];
            float a2 = Qs[ty * 4 + 2][kk];
            float a3 = Qs[ty * 4 + 3][kk];
            float4 bq = *(const float4*)&Kt[kk][tx * 4];
            s[0][0] = fmaf(a0, bq.x, s[0][0]); s[0][1] = fmaf(a0, bq.y, s[0][1]);
            s[0][2] = fmaf(a0, bq.z, s[0][2]); s[0][3] = fmaf(a0, bq.w, s[0][3]);
            s[1][0] = fmaf(a1, bq.x, s[1][0]); s[1][1] = fmaf(a1, bq.y, s[1][1]);
            s[1][2] = fmaf(a1, bq.z, s[1][2]); s[1][3] = fmaf(a1, bq.w, s[1][3]);
            s[2][0] = fmaf(a2, bq.x, s[2][0]); s[2][1] = fmaf(a2, bq.y, s[2][1]);
            s[2][2] = fmaf(a2, bq.z, s[2][2]); s[2][3] = fmaf(a2, bq.w, s[2][3]);
            s[3][0] = fmaf(a3, bq.x, s[3][0]); s[3][1] = fmaf(a3, bq.y, s[3][1]);
            s[3][2] = fmaf(a3, bq.z, s[3][2]); s[3][3] = fmaf(a3, bq.w, s[3][3]);
        }

        float p_[4][4];
        #pragma unroll
        for (int i = 0; i < 4; i++) {
            float rm = fmaxf(fmaxf(s[i][0], s[i][1]), fmaxf(s[i][2], s[i][3]));
            #pragma unroll
            for (int off = 8; off > 0; off >>= 1)
                rm = fmaxf(rm, __shfl_xor_sync(0xffffffffu, rm, off));
            float mnew = fmaxf(m_[i], rm);
            float alpha = __expf(m_[i] - mnew);
            float rs = 0.f;
            #pragma unroll
            for (int j = 0; j < 4; j++) {
                p_[i][j] = __expf(s[i][j] - mnew);
                rs += p_[i][j];
            }
            #pragma unroll
            for (int off = 8; off > 0; off >>= 1)
                rs += __shfl_xor_sync(0xffffffffu, rs, off);
            l_[i] = l_[i] * alpha + rs;
            m_[i] = mnew;
            #pragma unroll
            for (int j = 0; j < 4; j++) o_[i][j] *= alpha;
        }

        __syncthreads();
        #pragma unroll
        for (int i = 0; i < 4; i++)
            #pragma unroll
            for (int j = 0; j < 4; j++)
                Kt[ty * 4 + i][tx * 4 + j] = p_[i][j];
        __syncthreads();

        #pragma unroll 8
        for (int j = 0; j < 64; j++) {
            float4 v = *(const float4*)&Vs[j][tx * 4];
            float p0 = Kt[ty * 4 + 0][j];
            float p1 = Kt[ty * 4 + 1][j];
            float p2 = Kt[ty * 4 + 2][j];
            float p3 = Kt[ty * 4 + 3][j];
            o_[0][0] = fmaf(p0, v.x, o_[0][0]); o_[0][1] = fmaf(p0, v.y, o_[0][1]);
            o_[0][2] = fmaf(p0, v.z, o_[0][2]); o_[0][3] = fmaf(p0, v.w, o_[0][3]);
            o_[1][0] = fmaf(p1, v.x, o_[1][0]); o_[1][1] = fmaf(p1, v.y, o_[1][1]);
            o_[1][2] = fmaf(p1, v.z, o_[1][2]); o_[1][3] = fmaf(p1, v.w, o_[1][3]);
            o_[2][0] = fmaf(p2, v.x, o_[2][0]); o_[2][1] = fmaf(p2, v.y, o_[2][1]);
            o_[2][2] = fmaf(p2, v.z, o_[2][2]); o_[2][3] = fmaf(p2, v.w, o_[2][3]);
            o_[3][0] = fmaf(p3, v.x, o_[3][0]); o_[3][1] = fmaf(p3, v.y, o_[3][1]);
            o_[3][2] = fmaf(p3, v.z, o_[3][2]); o_[3][3] = fmaf(p3, v.w, o_[3][3]);
        }
    }

    // normalize + write bf16 hi/lo split (input to output GEMM)
    #pragma unroll
    for (int i = 0; i < 4; i++) {
        int row = ty * 4 + i;
        int t = g_tok[toff + qt * 64 + row];
        float inv = 1.f / l_[i];
        float v0 = o_[i][0] * inv, v1 = o_[i][1] * inv;
        float v2 = o_[i][2] * inv, v3 = o_[i][3] * inv;
        __nv_bfloat16 h0 = __float2bfloat16(v0);
        __nv_bfloat16 h1 = __float2bfloat16(v1);
        __nv_bfloat16 h2 = __float2bfloat16(v2);
        __nv_bfloat16 h3 = __float2bfloat16(v3);
        __nv_bfloat16 l0 = __float2bfloat16(v0 - __bfloat162float(h0));
        __nv_bfloat16 l1 = __float2bfloat16(v1 - __bfloat162float(h1));
        __nv_bfloat16 l2 = __float2bfloat16(v2 - __bfloat162float(h2));
        __nv_bfloat16 l3 = __float2bfloat16(v3 - __bfloat162float(h3));
        size_t base = ((size_t)bb * SEQ + t) * EMB + hd * DHEAD + tx * 4;
        __nv_bfloat162* hp = (__nv_bfloat162*)(g_ah + base);
        __nv_bfloat162* lp = (__nv_bfloat162*)(g_al + base);
        hp[0] = __halves2bfloat162(h0, h1);
        hp[1] = __halves2bfloat162(h2, h3);
        lp[0] = __halves2bfloat162(l0, l1);
        lp[1] = __halves2bfloat162(l2, l3);
    }
}

// ---------------------------------------------------------------------------
// Launch
// ---------------------------------------------------------------------------
extern "C" void kernel_launch(void* const* d_in, const int* in_sizes, int n_in,
                              void* d_out, int out_size)
{
    const float* x      = (const float*)d_in[0];
    const float* w_qkv  = (const float*)d_in[1];
    const float* b_qkv  = (const float*)d_in[2];
    const float* w_out  = (const float*)d_in[3];
    const float* b_out  = (const float*)d_in[4];
    float* out          = (float*)d_out;

    float *qkv_p;
    __nv_bfloat16 *xh_p, *xl_p, *wqh_p, *wql_p, *ah_p, *al_p, *woh_p, *wol_p;
    cudaGetSymbolAddress((void**)&qkv_p, g_qkv);
    cudaGetSymbolAddress((void**)&xh_p,  g_xh);
    cudaGetSymbolAddress((void**)&xl_p,  g_xl);
    cudaGetSymbolAddress((void**)&wqh_p, g_wqh);
    cudaGetSymbolAddress((void**)&wql_p, g_wql);
    cudaGetSymbolAddress((void**)&ah_p,  g_ah);
    cudaGetSymbolAddress((void**)&al_p,  g_al);
    cudaGetSymbolAddress((void**)&woh_p, g_woh);
    cudaGetSymbolAddress((void**)&wol_p, g_wol);

    cudaFuncSetAttribute(gemm_bf16x3_mma,
                         cudaFuncAttributeMaxDynamicSharedMemorySize, GEMM_SMEM);

    // Hilbert tables
    build_orders_kernel<<<16, 256>>>();
    build_tok_kernel<<<1, 1024>>>();

    // hi/lo splits of inputs and weights
    split_kernel<<<(MTOT * EMB / 4) / 256, 256>>>(x, xh_p, xl_p, MTOT * EMB / 4);
    split_kernel<<<(QKV_N * EMB / 4) / 256, 256>>>(w_qkv, wqh_p, wql_p, QKV_N * EMB / 4);
    split_kernel<<<(EMB * EMB / 4) / 256, 256>>>(w_out, woh_p, wol_p, EMB * EMB / 4);

    // QKV projection: [16384,1024] x [3072,1024]^T -> fp32 qkv
    {
        dim3 grid(QKV_N / 128, MTOT / 128);
        gemm_bf16x3_mma<<<grid, 256, GEMM_SMEM>>>(
            xh_p, xl_p, wqh_p, wql_p, b_qkv, qkv_p, MTOT, QKV_N, EMB);
    }

    // Segmented dilated attention
    {
        dim3 grid(128, BATCH * NHEAD);
        attn_kernel<<<grid, 256>>>();
    }

    // Output projection: [16384,1024] x [1024,1024]^T
    {
        dim3 grid(EMB / 128, MTOT / 128);
        gemm_bf16x3_mma<<<grid, 256, GEMM_SMEM>>>(
            ah_p, al_p, woh_p, wol_p, b_out, out, MTOT, EMB, EMB);
    }
}